// round 14
// baseline (speedup 1.0000x reference)
#include <cuda_runtime.h>
#include <cstdint>

#define FULL 0xffffffffu
typedef unsigned long long u64;

// ---- packed f32x2 helpers (Blackwell FFMA2 — only reachable via PTX) ----
__device__ __forceinline__ u64 pk2(float lo, float hi) {
    u64 r;
    asm("mov.b64 %0, {%1, %2};" : "=l"(r) : "f"(lo), "f"(hi));
    return r;
}
__device__ __forceinline__ float2 upk2(u64 p) {
    float2 v;
    asm("mov.b64 {%0, %1}, %2;" : "=f"(v.x), "=f"(v.y) : "l"(p));
    return v;
}
__device__ __forceinline__ u64 fma2(u64 a, u64 b, u64 c) {
    u64 d;
    asm("fma.rn.f32x2 %0, %1, %2, %3;" : "=l"(d) : "l"(a), "l"(b), "l"(c));
    return d;
}
__device__ __forceinline__ u64 mul2(u64 a, u64 b) {
    u64 d;
    asm("mul.rn.f32x2 %0, %1, %2;" : "=l"(d) : "l"(a), "l"(b));
    return d;
}

// Fused split-K kernel with TMA-engine bulk streams, 8 rows / 256-thread block.
// Both 32MB streams leave the LSU: x arrives via ONE cp.async.bulk (g->s, mbarrier)
// per block; out leaves via ONE cp.async.bulk (s->g, bulk_group) per block from an
// smem staging tile that ALIASES the x tile (barrier-separated).
// Phase 1 (per warp j-slice, W1 reg-resident): 8 rows x (1 LDS.128 + 16 FFMA2 +
//   8 FADD + 9-shuffle reduce-scatter + guarded STS).
// Quantum (threads 0..63): z = cos(th)cos(a) - sin(th)sin(phi)sin(a); CNOT ring
//   conjugated to Z-strings -> qout[0]=z1..z7, qout[i]=z0..zi (octet prefix scans).
// Phase 2: e = wid*128 + c*32 + lane; W2 reg-resident, bias folded; results to
//   smem staging via conflict-free STS.32, then bulk store.
__global__ void __launch_bounds__(256, 4)
ffq_kernel(const float* __restrict__ x,  const float* __restrict__ W1,
           const float* __restrict__ b1, const float* __restrict__ qp,
           const float* __restrict__ W2, const float* __restrict__ b2,
           float* __restrict__ out, int nrows)
{
    __shared__ __align__(16) float sx[8 * 1024];    // 32 KB x tile, reused as out staging
    __shared__ __align__(16) float part[8][8][8];   // [row][qubit][warp]
    __shared__ __align__(16) float sq[8][8];        // qout per row
    __shared__ __align__(8)  u64 mbar[1];

    const int tid  = threadIdx.x;
    const int lane = tid & 31;
    const int wid  = tid >> 5;
    const int rowblk = blockIdx.x * 8;
    const int nr = min(8, nrows - rowblk);
    const uint32_t tile_bytes = (uint32_t)nr * 4096u;

    const uint32_t mbar_a = (uint32_t)__cvta_generic_to_shared(mbar);
    const uint32_t sx_a   = (uint32_t)__cvta_generic_to_shared(sx);

    // ---------------- TMA bulk load of the x tile ----------------
    if (tid == 0) {
        asm volatile("mbarrier.init.shared.b64 [%0], 1;" :: "r"(mbar_a));
    }
    __syncthreads();
    if (tid == 0) {
        asm volatile("mbarrier.arrive.expect_tx.shared.b64 _, [%0], %1;"
                     :: "r"(mbar_a), "r"(tile_bytes) : "memory");
        asm volatile("cp.async.bulk.shared::cta.global.mbarrier::complete_tx::bytes "
                     "[%0], [%1], %2, [%3];"
                     :: "r"(sx_a), "l"(x + (size_t)rowblk * 1024),
                        "r"(tile_bytes), "r"(mbar_a) : "memory");
    }

    const int j0 = wid * 128 + lane * 4;   // this lane's 4 j's

    // W1 slice register-resident (LDG latency overlaps the bulk load)
    u64 wp0[8], wp1[8];
#pragma unroll
    for (int i = 0; i < 8; i++) {
        longlong2 w = __ldg((const longlong2*)(W1 + (size_t)i * 1024 + j0));
        wp0[i] = (u64)w.x;
        wp1[i] = (u64)w.y;
    }
    // W2 slice too (dead-cheap while waiting on the tile)
    u64 w2r[4][4];
    u64 bvp[4];
#pragma unroll
    for (int c = 0; c < 4; c++) {
        const int e = wid * 128 + c * 32 + lane;
        longlong2 a = __ldg((const longlong2*)(W2 + (size_t)e * 8));
        longlong2 b = __ldg((const longlong2*)(W2 + (size_t)e * 8 + 4));
        w2r[c][0] = (u64)a.x;
        w2r[c][1] = (u64)a.y;
        w2r[c][2] = (u64)b.x;
        w2r[c][3] = (u64)b.y;
        bvp[c] = pk2(__ldg(b2 + e), 0.0f);
    }

    // wait for the tile (parity 0)
    asm volatile(
        "{\n\t.reg .pred P;\n"
        "W%=:\n\t"
        "mbarrier.try_wait.parity.shared::cta.b64 P, [%0], 0;\n\t"
        "@P bra.uni D%=;\n\t"
        "bra.uni W%=;\n"
        "D%=:\n\t}"
        :: "r"(mbar_a) : "memory");

    // ---------------- Phase 1: split-K GEMM1 from smem ----------------
#pragma unroll 4
    for (int rloc = 0; rloc < 8; rloc++) {
        const longlong2 xv = *(const longlong2*)(sx + rloc * 1024 + j0); // LDS.128
        const u64 x0 = (u64)xv.x, x1 = (u64)xv.y;

        float v[8];
#pragma unroll
        for (int i = 0; i < 8; i++) {
            u64 s = mul2(x0, wp0[i]);
            s = fma2(x1, wp1[i], s);
            float2 f = upk2(s);
            v[i] = f.x + f.y;
        }

        // reduce-scatter over lane bits 0..2: lane L -> qubit index L&7
#pragma unroll
        for (int w = 4; w >= 1; w >>= 1) {
            const bool hi = (lane & w) != 0;
#pragma unroll
            for (int k = 0; k < w; k++) {
                float sendv = hi ? v[k] : v[k + w];
                float keepv = hi ? v[k + w] : v[k];
                v[k] = keepv + __shfl_xor_sync(FULL, sendv, w, 32);
            }
        }
        float s8 = v[0];
        s8 += __shfl_xor_sync(FULL, s8, 8, 32);
        s8 += __shfl_xor_sync(FULL, s8, 16, 32);

        if (lane < 8) part[rloc][lane][wid] = s8;
    }
    __syncthreads();

    // ---------------- Quantum: one thread per (row, qubit) ----------------
    if (tid < 64) {
        const int r  = tid >> 3;
        const int qi = tid & 7;

        const float4 pa = *(const float4*)&part[r][qi][0];
        const float4 pb = *(const float4*)&part[r][qi][4];
        const float a = ((pa.x + pa.y) + (pa.z + pa.w))
                      + ((pb.x + pb.y) + (pb.z + pb.w)) + __ldg(b1 + qi);

        const float phi   = __ldg(qp + 3 * qi);
        const float theta = __ldg(qp + 3 * qi + 1);
        const float k1 = cosf(theta);
        const float k2 = sinf(theta) * sinf(phi);

        float sa, ca;
        __sincosf(a, &sa, &ca);
        const float z = k1 * ca - k2 * sa;

        // inclusive prefix product over each 8-lane octet
        float p = z;
#pragma unroll
        for (int d = 1; d < 8; d <<= 1) {
            float t = __shfl_up_sync(FULL, p, d, 8);
            if (qi >= d) p *= t;
        }
        // second scan with z0 -> 1 for qout[0] = z1..z7
        float wv = (qi == 0) ? 1.0f : z;
#pragma unroll
        for (int d = 1; d < 8; d <<= 1) {
            float t = __shfl_up_sync(FULL, wv, d, 8);
            if (qi >= d) wv *= t;
        }
        const float pb7 = __shfl_sync(FULL, wv, 7, 8);
        sq[r][qi] = (qi == 0) ? pb7 : p;
    }
    __syncthreads();

    // ---------------- Phase 2: GEMM2 into the smem staging tile ----------------
#pragma unroll 4
    for (int rloc = 0; rloc < 8; rloc++) {
        const longlong2* sp = (const longlong2*)sq[rloc];   // broadcast LDS x2
        longlong2 qa = sp[0], qb = sp[1];
        const u64 qd0 = (u64)qa.x, qd1 = (u64)qa.y;
        const u64 qd2 = (u64)qb.x, qd3 = (u64)qb.y;

        float* srow = sx + rloc * 1024 + wid * 128 + lane;  // staging (aliases x tile)
#pragma unroll
        for (int c = 0; c < 4; c++) {
            u64 s = fma2(w2r[c][0], qd0, bvp[c]);
            s = fma2(w2r[c][1], qd1, s);
            s = fma2(w2r[c][2], qd2, s);
            s = fma2(w2r[c][3], qd3, s);
            float2 f = upk2(s);
            srow[c * 32] = f.x + f.y;   // conflict-free STS.32
        }
    }
    __syncthreads();

    // ---------------- TMA bulk store of the out tile ----------------
    if (tid == 0) {
        asm volatile("fence.proxy.async.shared::cta;" ::: "memory");
        asm volatile("cp.async.bulk.global.shared::cta.bulk_group [%0], [%1], %2;"
                     :: "l"(out + (size_t)rowblk * 1024), "r"(sx_a),
                        "r"(tile_bytes) : "memory");
        asm volatile("cp.async.bulk.commit_group;" ::: "memory");
        asm volatile("cp.async.bulk.wait_group.read 0;" ::: "memory");
    }
}

extern "C" void kernel_launch(void* const* d_in, const int* in_sizes, int n_in,
                              void* d_out, int out_size)
{
    const float* x  = (const float*)d_in[0];
    const float* W1 = (const float*)d_in[1];
    const float* b1 = (const float*)d_in[2];
    const float* qp = (const float*)d_in[3];
    const float* W2 = (const float*)d_in[4];
    const float* b2 = (const float*)d_in[5];
    float* out = (float*)d_out;

    const int nrows = in_sizes[0] / 1024;            // batch * seq_len
    const int nblocks = (nrows + 7) / 8;             // 8 rows per block

    ffq_kernel<<<nblocks, 256>>>(x, W1, b1, qp, W2, b2, out, nrows);
}

// round 15
// speedup vs baseline: 1.4307x; 1.4307x over previous
#include <cuda_runtime.h>
#include <cstdint>

#define FULL 0xffffffffu
typedef unsigned long long u64;

// ---- packed f32x2 helpers (Blackwell FFMA2 — only reachable via PTX) ----
__device__ __forceinline__ u64 pk2(float lo, float hi) {
    u64 r;
    asm("mov.b64 %0, {%1, %2};" : "=l"(r) : "f"(lo), "f"(hi));
    return r;
}
__device__ __forceinline__ float2 upk2(u64 p) {
    float2 v;
    asm("mov.b64 {%0, %1}, %2;" : "=f"(v.x), "=f"(v.y) : "l"(p));
    return v;
}
__device__ __forceinline__ u64 fma2(u64 a, u64 b, u64 c) {
    u64 d;
    asm("fma.rn.f32x2 %0, %1, %2, %3;" : "=l"(d) : "l"(a), "l"(b), "l"(c));
    return d;
}
__device__ __forceinline__ u64 mul2(u64 a, u64 b) {
    u64 d;
    asm("mul.rn.f32x2 %0, %1, %2;" : "=l"(d) : "l"(a), "l"(b));
    return d;
}

// Fused split-K kernel, 8 rows per 256-thread block (R6 structure) with one fix:
// W2's register fill had a 32B/lane stride -> 32 cache lines per LDG.128 ->
// 2048 L1 wavefronts per block (75% of all L1 work). W2 is now staged through
// smem with coalesced float4 copies (64 wavefronts), and the strided register
// fill hits smem (cheap, once per block).
// Phase 1: warp w owns j-slice [w*128,w*128+128); W1 slice register-resident.
//   Per row per lane: 1 LDG.128 (x), 16 FFMA2, 9-shuffle reduce-scatter, STS.
// Quantum (threads 0..63): z = cos(th)cos(a) - sin(th)sin(phi)sin(a);
//   CNOT ring conjugated to Z-strings -> qout via octet prefix products.
// Phase 2: e = wid*128 + c*32 + lane; W2 regs filled from smem; bias folded;
//   per row: 2 broadcast LDS + 16 FFMA2 + 4 coalesced STG.32.
__global__ void __launch_bounds__(256, 3)
ffq_kernel(const float* __restrict__ x,  const float* __restrict__ W1,
           const float* __restrict__ b1, const float* __restrict__ qp,
           const float* __restrict__ W2, const float* __restrict__ b2,
           float* __restrict__ out, int nrows)
{
    __shared__ __align__(16) float sW2[1024 * 8];   // staged W2 (32 KB)
    __shared__ __align__(16) float part[8][8][8];   // [row][qubit][warp]
    __shared__ __align__(16) float sq[8][8];        // qout per row

    const int tid  = threadIdx.x;
    const int lane = tid & 31;
    const int wid  = tid >> 5;
    const int rowblk = blockIdx.x * 8;

    // ---------------- Stage W2 into smem (coalesced float4) ----------------
#pragma unroll
    for (int k = 0; k < 8; k++) {
        const int idx = tid + k * 256;
        ((float4*)sW2)[idx] = __ldg(((const float4*)W2) + idx);
    }

    const int j0 = wid * 128 + lane * 4;   // this lane's 4 j's

    // ---------------- Phase 1: split-K GEMM1, W1 reg-resident ----------------
    u64 wp0[8], wp1[8];
#pragma unroll
    for (int i = 0; i < 8; i++) {
        longlong2 w = __ldg((const longlong2*)(W1 + (size_t)i * 1024 + j0));
        wp0[i] = (u64)w.x;
        wp1[i] = (u64)w.y;
    }

#pragma unroll 4
    for (int rloc = 0; rloc < 8; rloc++) {
        const int row = min(rowblk + rloc, nrows - 1);
        longlong2 xv = __ldg((const longlong2*)(x + (size_t)row * 1024 + j0));
        const u64 x0 = (u64)xv.x, x1 = (u64)xv.y;

        float v[8];
#pragma unroll
        for (int i = 0; i < 8; i++) {
            u64 s = mul2(x0, wp0[i]);
            s = fma2(x1, wp1[i], s);
            float2 f = upk2(s);
            v[i] = f.x + f.y;
        }

        // reduce-scatter over lane bits 0..2: lane L -> qubit index L&7
#pragma unroll
        for (int w = 4; w >= 1; w >>= 1) {
            const bool hi = (lane & w) != 0;
#pragma unroll
            for (int k = 0; k < w; k++) {
                float sendv = hi ? v[k] : v[k + w];
                float keepv = hi ? v[k + w] : v[k];
                v[k] = keepv + __shfl_xor_sync(FULL, sendv, w, 32);
            }
        }
        float s8 = v[0];
        s8 += __shfl_xor_sync(FULL, s8, 8, 32);
        s8 += __shfl_xor_sync(FULL, s8, 16, 32);

        if (lane < 8) part[rloc][lane][wid] = s8;
    }
    __syncthreads();   // covers part[] AND the sW2 staging stores

    // ---------------- Quantum: one thread per (row, qubit) ----------------
    if (tid < 64) {
        const int r  = tid >> 3;
        const int qi = tid & 7;

        const float4 pa = *(const float4*)&part[r][qi][0];
        const float4 pb = *(const float4*)&part[r][qi][4];
        const float a = ((pa.x + pa.y) + (pa.z + pa.w))
                      + ((pb.x + pb.y) + (pb.z + pb.w)) + __ldg(b1 + qi);

        const float phi   = __ldg(qp + 3 * qi);
        const float theta = __ldg(qp + 3 * qi + 1);
        const float k1 = cosf(theta);
        const float k2 = sinf(theta) * sinf(phi);

        float sa, ca;
        __sincosf(a, &sa, &ca);
        const float z = k1 * ca - k2 * sa;

        // inclusive prefix product over each 8-lane octet
        float p = z;
#pragma unroll
        for (int d = 1; d < 8; d <<= 1) {
            float t = __shfl_up_sync(FULL, p, d, 8);
            if (qi >= d) p *= t;
        }
        // second scan with z0 -> 1 for qout[0] = z1..z7
        float wv = (qi == 0) ? 1.0f : z;
#pragma unroll
        for (int d = 1; d < 8; d <<= 1) {
            float t = __shfl_up_sync(FULL, wv, d, 8);
            if (qi >= d) wv *= t;
        }
        const float pb7 = __shfl_sync(FULL, wv, 7, 8);
        sq[r][qi] = (qi == 0) ? pb7 : p;
    }
    __syncthreads();

    // ---------------- Phase 2: GEMM2, W2 regs filled from smem ----------------
    u64 w2r[4][4];
    u64 bvp[4];
#pragma unroll
    for (int c = 0; c < 4; c++) {
        const int e = wid * 128 + c * 32 + lane;
        const longlong2* ws = (const longlong2*)(sW2 + (size_t)e * 8);
        longlong2 a = ws[0];           // LDS.128 (bank conflicts OK: once per block)
        longlong2 b = ws[1];
        w2r[c][0] = (u64)a.x;
        w2r[c][1] = (u64)a.y;
        w2r[c][2] = (u64)b.x;
        w2r[c][3] = (u64)b.y;
        bvp[c] = pk2(__ldg(b2 + e), 0.0f);
    }

#pragma unroll 4
    for (int rloc = 0; rloc < 8; rloc++) {
        const int row = rowblk + rloc;
        if (row >= nrows) break;

        const longlong2* sp = (const longlong2*)sq[rloc];   // broadcast LDS x2
        longlong2 qa = sp[0], qb = sp[1];
        const u64 qd0 = (u64)qa.x, qd1 = (u64)qa.y;
        const u64 qd2 = (u64)qb.x, qd3 = (u64)qb.y;

        float* orow = out + (size_t)row * 1024 + wid * 128 + lane;
#pragma unroll
        for (int c = 0; c < 4; c++) {
            u64 s = fma2(w2r[c][0], qd0, bvp[c]);
            s = fma2(w2r[c][1], qd1, s);
            s = fma2(w2r[c][2], qd2, s);
            s = fma2(w2r[c][3], qd3, s);
            float2 f = upk2(s);
            orow[c * 32] = f.x + f.y;
        }
    }
}

extern "C" void kernel_launch(void* const* d_in, const int* in_sizes, int n_in,
                              void* d_out, int out_size)
{
    const float* x  = (const float*)d_in[0];
    const float* W1 = (const float*)d_in[1];
    const float* b1 = (const float*)d_in[2];
    const float* qp = (const float*)d_in[3];
    const float* W2 = (const float*)d_in[4];
    const float* b2 = (const float*)d_in[5];
    float* out = (float*)d_out;

    const int nrows = in_sizes[0] / 1024;            // batch * seq_len
    const int nblocks = (nrows + 7) / 8;             // 8 rows per block

    ffq_kernel<<<nblocks, 256>>>(x, W1, b1, qp, W2, b2, out, nrows);
}